// round 10
// baseline (speedup 1.0000x reference)
#include <cuda_runtime.h>

typedef unsigned long long ull;

// ---- packed f32x2 helpers ----
__device__ __forceinline__ ull pk(float lo, float hi){
  ull r; asm("mov.b64 %0, {%1, %2};" : "=l"(r) : "f"(lo), "f"(hi)); return r;
}
__device__ __forceinline__ float2 upk(ull v){
  float2 r; asm("mov.b64 {%0, %1}, %2;" : "=f"(r.x), "=f"(r.y) : "l"(v)); return r;
}
__device__ __forceinline__ ull f2fma(ull a, ull b, ull c){
  ull d; asm("fma.rn.f32x2 %0, %1, %2, %3;" : "=l"(d) : "l"(a), "l"(b), "l"(c)); return d;
}
__device__ __forceinline__ ull f2mul(ull a, ull b){
  ull d; asm("mul.rn.f32x2 %0, %1, %2;" : "=l"(d) : "l"(a), "l"(b)); return d;
}

// ---- cp.async helpers ----
__device__ __forceinline__ void cpa16(unsigned d, const float* g, int srcsz){
  asm volatile("cp.async.cg.shared.global [%0], [%1], 16, %2;"
               :: "r"(d), "l"(g), "r"(srcsz));
}
__device__ __forceinline__ void cpa_commit(){
  asm volatile("cp.async.commit_group;");
}
template<int N> __device__ __forceinline__ void cpa_waitg(){
  asm volatile("cp.async.wait_group %0;" :: "n"(N));
}

namespace cv {
constexpr int B = 4, C = 128, H = 128, W = 256, D = 81;
constexpr int HT = 2;      // output rows per block
constexpr int WT = 64;     // output cols per block
constexpr int PX = 8;      // pixels per thread
constexpr int XR = 10;     // x2 halo rows
constexpr int XC = 104;    // x2 smem row stride (floats); cols cover [w0-16,w0+80)
constexpr int NT = 144;    // 8 w-groups * 2 h * 9 i
constexpr int PIPE = 4;
constexpr int CPB = 2;     // channels per slot
constexpr int HW = H * W;
constexpr int CH2F = XR * XC;        // 1040
constexpr int CH1F = HT * WT;        // 128
constexpr int SLOT2F = CPB * CH2F;   // 2080
constexpr int SLOT1F = CPB * CH1F;   // 256
}
using namespace cv;

__global__ __launch_bounds__(NT, 3)
void costvol_kernel(const float* __restrict__ x1g,
                    const float* __restrict__ x2g,
                    float* __restrict__ outg)
{
  __shared__ __align__(16) float x2s[PIPE][CPB][XR][XC];  // 33.3 KB
  __shared__ __align__(16) float x1s[PIPE][CPB][HT][WT];  //  4.0 KB
  __shared__ __align__(16) float dummy16[4];

  const int tid = threadIdx.x;
  const int tc  = tid & 7;           // w-group: pixels w0+8*tc .. +7
  const int hl  = (tid >> 3) & 1;    // local h row
  const int ig  = tid >> 4;          // i-group 0..8; i = ig - 4

  const int w0 = blockIdx.x * WT;
  const int h0 = blockIdx.y * HT;
  const int b  = blockIdx.z;
  const int cbase = b * C * HW;

  // ---------- two uniform 16B staging tasks per thread ----------
  unsigned sb[2]; int szcp[2]; unsigned qstr[2], slstr[2]; const float* gp[2];
  #pragma unroll
  for (int t = 0; t < 2; t++){
    const int idx = tid + t * NT;
    if (idx < 240){                       // x2 halo chunk
      const int r  = idx / 24;
      const int c4 = idx - r * 24;
      const int gh = h0 - 4 + r;
      const int gw = w0 - 16 + 4 * c4;
      const bool v = ((unsigned)gh < (unsigned)H) && ((unsigned)gw < (unsigned)W);
      sb[t]    = (unsigned)__cvta_generic_to_shared(&x2s[0][0][r][4 * c4]);
      szcp[t]  = v ? 16 : 0;
      qstr[t]  = CH2F * 4;  slstr[t] = SLOT2F * 4;
      gp[t]    = x2g + cbase + (v ? (gh * W + gw) : 0);
    } else if (idx < 272){                // x1 chunk
      const int k = idx - 240;
      sb[t]    = (unsigned)__cvta_generic_to_shared(&x1s[0][0][k >> 4][4 * (k & 15)]);
      szcp[t]  = 16;
      qstr[t]  = CH1F * 4;  slstr[t] = SLOT1F * 4;
      gp[t]    = x1g + cbase + (h0 + (k >> 4)) * W + w0 + 4 * (k & 15);
    } else {                              // dummy (never dereferenced: srcsz=0)
      sb[t]    = (unsigned)__cvta_generic_to_shared(&dummy16[0]);
      szcp[t]  = 0;  qstr[t] = 0;  slstr[t] = 0;
      gp[t]    = x2g;
    }
  }

#define ISSUE(S) do{ \
  cpa16(sb[0] + (S) * slstr[0], gp[0], szcp[0]); \
  cpa16(sb[0] + (S) * slstr[0] + qstr[0], gp[0] + HW, szcp[0]); \
  cpa16(sb[1] + (S) * slstr[1], gp[1], szcp[1]); \
  cpa16(sb[1] + (S) * slstr[1] + qstr[1], gp[1] + HW, szcp[1]); \
  cpa_commit(); gp[0] += 2 * HW; gp[1] += 2 * HW; }while(0)

  // fixed per-thread smem read bases
  const float* x1c = &x1s[0][0][hl][8 * tc];
  const float* x2c = &x2s[0][0][hl + 8 - ig][8 * tc + 12];

  // 9 j * 4 w-pairs packed accumulators (72 regs)
  ull acc[9][4];
  #pragma unroll
  for (int jj = 0; jj < 9; jj++)
    #pragma unroll
    for (int p = 0; p < 4; p++) acc[jj][p] = 0ull;

#define COMP(S) do{ \
  _Pragma("unroll") \
  for (int q = 0; q < CPB; q++){ \
    const float* a1 = x1c + (S) * SLOT1F + q * CH1F; \
    const ulonglong2 av0 = *(const ulonglong2*)(a1); \
    const ulonglong2 av1 = *(const ulonglong2*)(a1 + 4); \
    const ull ap[4] = {av0.x, av0.y, av1.x, av1.y}; \
    const float* rp = x2c + (S) * SLOT2F + q * CH2F; \
    const ulonglong2 e0 = *(const ulonglong2*)(rp); \
    const ulonglong2 e1 = *(const ulonglong2*)(rp + 4); \
    const ulonglong2 e2 = *(const ulonglong2*)(rp + 8); \
    const ulonglong2 e3 = *(const ulonglong2*)(rp + 12); \
    ull pr[15]; \
    pr[0]  = e0.x; pr[2]  = e0.y; pr[4]  = e1.x; pr[6]  = e1.y; \
    pr[8]  = e2.x; pr[10] = e2.y; pr[12] = e3.x; pr[14] = e3.y; \
    pr[1]  = pk(upk(e0.x).y, upk(e0.y).x); \
    pr[3]  = pk(upk(e0.y).y, upk(e1.x).x); \
    pr[5]  = pk(upk(e1.x).y, upk(e1.y).x); \
    pr[7]  = pk(upk(e1.y).y, upk(e2.x).x); \
    pr[9]  = pk(upk(e2.x).y, upk(e2.y).x); \
    pr[11] = pk(upk(e2.y).y, upk(e3.x).x); \
    pr[13] = pk(upk(e3.x).y, upk(e3.y).x); \
    _Pragma("unroll") \
    for (int jj = 0; jj < 9; jj++){ \
      _Pragma("unroll") \
      for (int p = 0; p < 4; p++) \
        acc[jj][p] = f2fma(ap[p], pr[2 * p + 8 - jj], acc[jj][p]); \
    } \
  } }while(0)

  // ---------------- software pipeline: 64 slot-iterations ----------------
  ISSUE(0); ISSUE(1); ISSUE(2);

  #pragma unroll 1
  for (int o = 0; o < 15; o++){
    cpa_waitg<2>(); __syncthreads(); ISSUE(3); COMP(0);
    cpa_waitg<2>(); __syncthreads(); ISSUE(0); COMP(1);
    cpa_waitg<2>(); __syncthreads(); ISSUE(1); COMP(2);
    cpa_waitg<2>(); __syncthreads(); ISSUE(2); COMP(3);
  }
  cpa_waitg<2>(); __syncthreads(); ISSUE(3); COMP(0);
  cpa_waitg<2>(); __syncthreads();           COMP(1);
  cpa_waitg<1>(); __syncthreads();           COMP(2);
  cpa_waitg<0>(); __syncthreads();           COMP(3);

#undef ISSUE
#undef COMP

  // ---------------- epilogue: scale by 1/81, packed stores ----------------
  const ull invD2 = pk(1.0f / 81.0f, 1.0f / 81.0f);
  const int i = ig - 4;
  const int h = h0 + hl;
  const int w = w0 + 8 * tc;
  #pragma unroll
  for (int jj = 0; jj < 9; jj++){
    const int j = jj - 4;
    const int k = (9 * i + j + 81) % 81;   // python-mod wraparound
    const size_t idx = ((size_t)(b * D + k) * H + h) * W + w;
    ulonglong2 o0, o1;
    o0.x = f2mul(acc[jj][0], invD2);  o0.y = f2mul(acc[jj][1], invD2);
    o1.x = f2mul(acc[jj][2], invD2);  o1.y = f2mul(acc[jj][3], invD2);
    *(ulonglong2*)&outg[idx]     = o0;
    *(ulonglong2*)&outg[idx + 4] = o1;
  }
}

extern "C" void kernel_launch(void* const* d_in, const int* in_sizes, int n_in,
                              void* d_out, int out_size)
{
  const float* x1 = (const float*)d_in[0];
  const float* x2 = (const float*)d_in[1];
  float* out = (float*)d_out;
  dim3 grid(W / WT, H / HT, B);   // (4, 64, 4) = 1024 blocks
  costvol_kernel<<<grid, NT>>>(x1, x2, out);
}

// round 12
// speedup vs baseline: 1.3212x; 1.3212x over previous
#include <cuda_runtime.h>

typedef unsigned long long ull;

// ---- packed f32x2 helpers ----
__device__ __forceinline__ ull pk(float lo, float hi){
  ull r; asm("mov.b64 %0, {%1, %2};" : "=l"(r) : "f"(lo), "f"(hi)); return r;
}
__device__ __forceinline__ float2 upk(ull v){
  float2 r; asm("mov.b64 {%0, %1}, %2;" : "=f"(r.x), "=f"(r.y) : "l"(v)); return r;
}
__device__ __forceinline__ ull f2fma(ull a, ull b, ull c){
  ull d; asm("fma.rn.f32x2 %0, %1, %2, %3;" : "=l"(d) : "l"(a), "l"(b), "l"(c)); return d;
}

// ---- cp.async helpers ----
__device__ __forceinline__ void cpa16(unsigned d, const float* g, int srcsz){
  asm volatile("cp.async.cg.shared.global [%0], [%1], 16, %2;"
               :: "r"(d), "l"(g), "r"(srcsz));
}
__device__ __forceinline__ void cpa_commit(){
  asm volatile("cp.async.commit_group;");
}
template<int N> __device__ __forceinline__ void cpa_waitg(){
  asm volatile("cp.async.wait_group %0;" :: "n"(N));
}

namespace cv {
constexpr int B = 4, C = 128, H = 128, W = 256, D = 81;
constexpr int HT = 2;      // output rows per block
constexpr int WT = 64;     // output cols per block
constexpr int XR = 10;     // x2 halo rows
constexpr int XC = 104;    // x2 smem row stride (floats); cols cover [w0-16,w0+80)
constexpr int NT = 288;    // 16 w-groups * 2 h * 9 i
constexpr int PIPE = 4;
constexpr int CPB = 4;     // channels per slot
constexpr int HW = H * W;
constexpr int CH2F = XR * XC;        // 1040
constexpr int CH1F = HT * WT;        // 128
constexpr int SLOT2F = CPB * CH2F;   // 4160
constexpr int SLOT1F = CPB * CH1F;   // 512
constexpr int X2F = PIPE * SLOT2F;   // 16640
constexpr int X1F = PIPE * SLOT1F;   // 2048
constexpr int SMEMF = X2F + X1F + 4; // + dummy
constexpr int SMEMB = SMEMF * 4;     // 74768 bytes
}
using namespace cv;

__global__ __launch_bounds__(NT, 2)
void costvol_kernel(const float* __restrict__ x1g,
                    const float* __restrict__ x2g,
                    float* __restrict__ outg)
{
  extern __shared__ __align__(16) float smem[];
  float* x2b = smem;            // [PIPE][CPB][XR][XC]
  float* x1b = smem + X2F;      // [PIPE][CPB][HT][WT]
  float* dmb = smem + X2F + X1F;

  const int tid = threadIdx.x;
  const int tc  = tid & 15;          // w-group: pixels w0+4*tc .. +3
  const int hl  = (tid >> 4) & 1;    // local h row
  const int ig  = tid >> 5;          // warp id; i = ig - 4

  const int w0 = blockIdx.x * WT;
  const int h0 = blockIdx.y * HT;
  const int b  = blockIdx.z;
  const int cbase = b * C * HW;

  // ---------- uniform one-chunk-per-thread staging descriptor ----------
  unsigned sb; int szcp; unsigned qstr, slstr; const float* gp;
  if (tid < 240){                       // x2 halo chunk
    const int r  = tid / 24;
    const int c4 = tid - r * 24;
    const int gh = h0 - 4 + r;
    const int gw = w0 - 16 + 4 * c4;
    const bool v = ((unsigned)gh < (unsigned)H) && ((unsigned)gw < (unsigned)W);
    sb    = (unsigned)__cvta_generic_to_shared(x2b + r * XC + 4 * c4);
    szcp  = v ? 16 : 0;
    qstr  = CH2F * 4;  slstr = SLOT2F * 4;
    gp    = x2g + cbase + (v ? (gh * W + gw) : 0);
  } else if (tid < 272){                // x1 chunk
    const int k = tid - 240;
    sb    = (unsigned)__cvta_generic_to_shared(x1b + (k >> 4) * WT + 4 * (k & 15));
    szcp  = 16;
    qstr  = CH1F * 4;  slstr = SLOT1F * 4;
    gp    = x1g + cbase + (h0 + (k >> 4)) * W + w0 + 4 * (k & 15);
  } else {                              // dummy (srcsz=0 -> zfill, never deref)
    sb    = (unsigned)__cvta_generic_to_shared(dmb);
    szcp  = 0;  qstr = 0;  slstr = 0;
    gp    = x2g;
  }

#define ISSUE(S) do{ \
  cpa16(sb + (S) * slstr,            gp,          szcp); \
  cpa16(sb + (S) * slstr +     qstr, gp +     HW, szcp); \
  cpa16(sb + (S) * slstr + 2 * qstr, gp + 2 * HW, szcp); \
  cpa16(sb + (S) * slstr + 3 * qstr, gp + 3 * HW, szcp); \
  cpa_commit(); gp += 4 * HW; }while(0)

  // fixed per-thread smem read bases
  const float* x1c = x1b + hl * WT + 4 * tc;
  const float* x2c = x2b + (hl + 8 - ig) * XC + 4 * tc + 12;

  // accumulators: even jj = 2 packed pairs; odd jj = mid pair + 2 scalar edges
  ull   accE[5][2];   // jj = 0,2,4,6,8 : pixels (p0,p1),(p2,p3)
  ull   accM[4];      // jj = 1,3,5,7   : pixels (p1,p2)
  float accO[4][2];   // jj = 1,3,5,7   : pixels p0, p3
  #pragma unroll
  for (int e = 0; e < 5; e++){ accE[e][0] = 0ull; accE[e][1] = 0ull; }
  #pragma unroll
  for (int u = 0; u < 4; u++){ accM[u] = 0ull; accO[u][0] = 0.f; accO[u][1] = 0.f; }

#define COMP(S) do{ \
  _Pragma("unroll") \
  for (int q = 0; q < CPB; q++){ \
    const ulonglong2 av = *(const ulonglong2*)(x1c + (S) * SLOT1F + q * CH1F); \
    const ull ap0 = av.x, ap1 = av.y; \
    const float2 a0f = upk(ap0), a1f = upk(ap1); \
    const ull am = pk(a0f.y, a1f.x);            /* (a1,a2): 2 MOVs, reused 4x */ \
    const float* rp = x2c + (S) * SLOT2F + q * CH2F; \
    const ulonglong2 e0 = *(const ulonglong2*)(rp); \
    const ulonglong2 e1 = *(const ulonglong2*)(rp + 4); \
    const ulonglong2 e2 = *(const ulonglong2*)(rp + 8); \
    const ull pE[6] = {e0.x, e0.y, e1.x, e1.y, e2.x, e2.y}; \
    _Pragma("unroll") \
    for (int e = 0; e < 5; e++){                 /* jj = 2e (even) */ \
      accE[e][0] = f2fma(ap0, pE[4 - e], accE[e][0]); \
      accE[e][1] = f2fma(ap1, pE[5 - e], accE[e][1]); \
    } \
    _Pragma("unroll") \
    for (int u = 0; u < 4; u++){                 /* jj = 2u+1 (odd) */ \
      accM[u]    = f2fma(am, pE[4 - u], accM[u]); \
      accO[u][0] = fmaf(a0f.x, upk(pE[3 - u]).y, accO[u][0]); \
      accO[u][1] = fmaf(a1f.y, upk(pE[5 - u]).x, accO[u][1]); \
    } \
  } }while(0)

  // ---------------- software pipeline: 32 slot-iterations ----------------
  ISSUE(0); ISSUE(1); ISSUE(2);

  #pragma unroll 1
  for (int o = 0; o < 7; o++){
    cpa_waitg<2>(); __syncthreads(); ISSUE(3); COMP(0);
    cpa_waitg<2>(); __syncthreads(); ISSUE(0); COMP(1);
    cpa_waitg<2>(); __syncthreads(); ISSUE(1); COMP(2);
    cpa_waitg<2>(); __syncthreads(); ISSUE(2); COMP(3);
  }
  cpa_waitg<2>(); __syncthreads(); ISSUE(3); COMP(0);   // s=28 issues block 31
  cpa_waitg<2>(); __syncthreads();           COMP(1);
  cpa_waitg<1>(); __syncthreads();           COMP(2);
  cpa_waitg<0>(); __syncthreads();           COMP(3);

#undef ISSUE
#undef COMP

  // ---------------- epilogue: scale by 1/81 and store ----------------
  const float invD = 1.0f / 81.0f;
  const int i = ig - 4;
  const int h = h0 + hl;
  const int w = w0 + 4 * tc;

  #pragma unroll
  for (int e = 0; e < 5; e++){           // even jj = 2e, j = 2e-4
    const int k = (9 * i + (2 * e - 4) + 81) % 81;
    const float2 p0 = upk(accE[e][0]);
    const float2 p1 = upk(accE[e][1]);
    const float4 o = make_float4(p0.x * invD, p0.y * invD,
                                 p1.x * invD, p1.y * invD);
    *(float4*)&outg[((size_t)(b * D + k) * H + h) * W + w] = o;
  }
  #pragma unroll
  for (int u = 0; u < 4; u++){           // odd jj = 2u+1, j = 2u-3
    const int k = (9 * i + (2 * u - 3) + 81) % 81;
    const float2 pm = upk(accM[u]);
    const float4 o = make_float4(accO[u][0] * invD, pm.x * invD,
                                 pm.y * invD,       accO[u][1] * invD);
    *(float4*)&outg[((size_t)(b * D + k) * H + h) * W + w] = o;
  }
}

extern "C" void kernel_launch(void* const* d_in, const int* in_sizes, int n_in,
                              void* d_out, int out_size)
{
  const float* x1 = (const float*)d_in[0];
  const float* x2 = (const float*)d_in[1];
  float* out = (float*)d_out;
  cudaFuncSetAttribute(costvol_kernel,
                       cudaFuncAttributeMaxDynamicSharedMemorySize, SMEMB);
  dim3 grid(W / WT, H / HT, B);   // (4, 64, 4) = 1024 blocks
  costvol_kernel<<<grid, NT, SMEMB>>>(x1, x2, out);
}